// round 5
// baseline (speedup 1.0000x reference)
#include <cuda_runtime.h>
#include <math.h>
#include <stdint.h>

// ---------------- static scratch ----------------
__device__ float g_scratch[51904512];
__device__ float g_params[8][16];

static const size_t OFF_AUX  = 0;         // 8192 rows x 8 floats
static const size_t OFF_WM   = 65536;     // 4 x 1024 x 1024
static const size_t OFF_NX   = 4259840;   // 4096 x 768
static const size_t OFF_NS   = 7405568;
static const size_t OFF_Q    = 10551296;
static const size_t OFF_KV   = 13697024;  // 4096 x 1536
static const size_t OFF_ATT  = 19988480;
static const size_t OFF_P0   = 23134208;
static const size_t OFF_Z0   = 26279936;
static const size_t OFF_HID  = 29425664;  // 4096 x 1536
static const size_t OFF_WQT  = 35717120;
static const size_t OFF_WKVT = 36306944;  // 1536 x 768
static const size_t OFF_WPT  = 37486592;
static const size_t OFF_W1T  = 38076416;  // 1536 x 768
static const size_t OFF_W2T  = 39256064;  // 768 x 1536
static const size_t OFF_BQ2  = 40435712;
static const size_t OFF_BKV2 = 40436480;

// =========================================================================
// helpers
// =========================================================================
__device__ __forceinline__ uint32_t f2tf32(float f) {
    uint32_t u;
    asm("cvt.rna.tf32.f32 %0, %1;" : "=r"(u) : "f"(f));
    return u;
}

__device__ __forceinline__ void mma_tf32(float d[4], const uint32_t a[4], const uint32_t b[2]) {
    asm volatile(
        "mma.sync.aligned.m16n8k8.row.col.f32.tf32.tf32.f32 "
        "{%0,%1,%2,%3}, {%4,%5,%6,%7}, {%8,%9}, {%0,%1,%2,%3};"
        : "+f"(d[0]), "+f"(d[1]), "+f"(d[2]), "+f"(d[3])
        : "r"(a[0]), "r"(a[1]), "r"(a[2]), "r"(a[3]), "r"(b[0]), "r"(b[1]));
}

// =========================================================================
// weight transpose with optional per-row scale: out[c][r] = in[r][c] * g[r]
// =========================================================================
__global__ void transpose_scale_kernel(const float* __restrict__ in,
                                       const float* __restrict__ g,
                                       float* __restrict__ out, int R, int C) {
    __shared__ float t[32][33];
    int c0 = blockIdx.x << 5, r0 = blockIdx.y << 5;
    int tx = threadIdx.x, ty = threadIdx.y;
    float s = g ? g[r0 + ty] : 1.0f;
    t[ty][tx] = in[(size_t)(r0 + ty) * C + c0 + tx] * s;
    __syncthreads();
    out[(size_t)(c0 + ty) * R + r0 + tx] = t[tx][ty];
}

// =========================================================================
// bias fold: out[n] = b[n] + sum_j lnb[j] * W[j][n]
// =========================================================================
__global__ void fold_bias_kernel(const float* __restrict__ b, const float* __restrict__ lnb,
                                 const float* __restrict__ W, float* __restrict__ out,
                                 int Jdim, int N) {
    int n = blockIdx.x * 256 + threadIdx.x;
    if (n >= N) return;
    float acc = b[n];
    for (int j = 0; j < Jdim; j++) acc += lnb[j] * W[(size_t)j * N + n];
    out[n] = acc;
}

// =========================================================================
// mma.sync tf32 GEMM with register prefetch; 128x128 tile; occupancy 2
// =========================================================================
__global__ __launch_bounds__(256, 2) void gemm_mma_kernel(
    const float* __restrict__ A, const float* __restrict__ Bt,
    const float* __restrict__ bias, float* __restrict__ C,
    int M, int N, int K, int act) {
    __shared__ uint32_t As[128][36];
    __shared__ uint32_t Bs[128][36];

    int tid = threadIdx.x;
    int lane = tid & 31, warp = tid >> 5;
    int wm = warp >> 2, wn = warp & 3;
    int g = lane >> 2, t4 = lane & 3;
    int m0 = blockIdx.y << 7, n0 = blockIdx.x << 7;

    float acc[4][4][4];
#pragma unroll
    for (int i = 0; i < 4; i++)
#pragma unroll
        for (int j = 0; j < 4; j++)
#pragma unroll
            for (int r = 0; r < 4; r++) acc[i][j][r] = 0.f;

    int rowL[4], qL[4];
#pragma unroll
    for (int it = 0; it < 4; it++) {
        int e = (it << 8) + tid;
        rowL[it] = e >> 3;
        qL[it] = (e & 7) << 2;
    }

    float4 ra[4], rb[4];
#pragma unroll
    for (int it = 0; it < 4; it++) {
        ra[it] = *(const float4*)(A + (size_t)(m0 + rowL[it]) * K + qL[it]);
        rb[it] = *(const float4*)(Bt + (size_t)(n0 + rowL[it]) * K + qL[it]);
    }

    const int NT = K >> 5;
    for (int kt = 0; kt < NT; kt++) {
#pragma unroll
        for (int it = 0; it < 4; it++) {
            int row = rowL[it], q = qL[it];
            As[row][q + 0] = f2tf32(ra[it].x);
            As[row][q + 1] = f2tf32(ra[it].y);
            As[row][q + 2] = f2tf32(ra[it].z);
            As[row][q + 3] = f2tf32(ra[it].w);
            Bs[row][q + 0] = f2tf32(rb[it].x);
            Bs[row][q + 1] = f2tf32(rb[it].y);
            Bs[row][q + 2] = f2tf32(rb[it].z);
            Bs[row][q + 3] = f2tf32(rb[it].w);
        }
        __syncthreads();

        if (kt + 1 < NT) {
            int kbase = (kt + 1) << 5;
#pragma unroll
            for (int it = 0; it < 4; it++) {
                ra[it] = *(const float4*)(A + (size_t)(m0 + rowL[it]) * K + kbase + qL[it]);
                rb[it] = *(const float4*)(Bt + (size_t)(n0 + rowL[it]) * K + kbase + qL[it]);
            }
        }

#pragma unroll
        for (int kf = 0; kf < 4; kf++) {
            int kc = kf << 3;
            uint32_t af[4][4], bf[4][2];
#pragma unroll
            for (int mi = 0; mi < 4; mi++) {
                int row = (wm << 6) + (mi << 4) + g;
                af[mi][0] = As[row][kc + t4];
                af[mi][1] = As[row + 8][kc + t4];
                af[mi][2] = As[row][kc + t4 + 4];
                af[mi][3] = As[row + 8][kc + t4 + 4];
            }
#pragma unroll
            for (int ni = 0; ni < 4; ni++) {
                int nr = (wn << 5) + (ni << 3) + g;
                bf[ni][0] = Bs[nr][kc + t4];
                bf[ni][1] = Bs[nr][kc + t4 + 4];
            }
#pragma unroll
            for (int mi = 0; mi < 4; mi++)
#pragma unroll
                for (int ni = 0; ni < 4; ni++)
                    mma_tf32(acc[mi][ni], af[mi], bf[ni]);
        }
        __syncthreads();
    }

#pragma unroll
    for (int mi = 0; mi < 4; mi++) {
        int row0 = m0 + (wm << 6) + (mi << 4) + g;
#pragma unroll
        for (int ni = 0; ni < 4; ni++) {
            int col = n0 + (wn << 5) + (ni << 3) + (t4 << 1);
            float b0 = bias[col], b1 = bias[col + 1];
#pragma unroll
            for (int half = 0; half < 2; half++) {
                int row = row0 + half * 8;
                float v0 = acc[mi][ni][half * 2 + 0] + b0;
                float v1 = acc[mi][ni][half * 2 + 1] + b1;
                if (act) {
                    v0 = 0.5f * v0 * (1.0f + erff(v0 * 0.70710678118654752f));
                    v1 = 0.5f * v1 * (1.0f + erff(v1 * 0.70710678118654752f));
                }
                float2 st = make_float2(v0, v1);
                *(float2*)(C + (size_t)row * N + col) = st;
            }
        }
    }
}

// =========================================================================
// mma.sync flash attention, Q fragments in registers, occupancy 2
// dyn smem (u32): Ks[64][68]@0  VTs[64][68]@4352  Ws(f32)[128][66]@8704
//                 Ps[128][68]@17152  -> total 25856 u32 = 103424 B
// =========================================================================
__global__ __launch_bounds__(256, 2) void attn_mma_kernel(
    const float* __restrict__ q, const float* __restrict__ kv,
    const float* __restrict__ wm, float* __restrict__ att_out) {
    extern __shared__ uint32_t dynsm[];
    uint32_t (*Ks)[68]  = (uint32_t(*)[68])(dynsm);
    uint32_t (*VTs)[68] = (uint32_t(*)[68])(dynsm + 4352);
    float    (*Ws)[66]  = (float(*)[66])(dynsm + 8704);
    uint32_t (*Ps)[68]  = (uint32_t(*)[68])(dynsm + 17152);

    int bh = blockIdx.y;
    int b = bh / 12, h = bh - b * 12;
    int q0 = blockIdx.x << 7;
    int tid = threadIdx.x;
    int lane = tid & 31, warp = tid >> 5;
    int g = lane >> 2, t4 = lane & 3;
    int r = (warp << 4) + g;

    // Q fragments in registers (scale folded)
    uint32_t qf[8][4];
    {
        const float* qr0 = q + (size_t)(b * 1024 + q0 + r) * 768 + h * 64;
        const float* qr1 = qr0 + 8 * 768;
#pragma unroll
        for (int kf = 0; kf < 8; kf++) {
            int kc = kf << 3;
            qf[kf][0] = f2tf32(qr0[kc + t4] * 0.125f);
            qf[kf][1] = f2tf32(qr1[kc + t4] * 0.125f);
            qf[kf][2] = f2tf32(qr0[kc + t4 + 4] * 0.125f);
            qf[kf][3] = f2tf32(qr1[kc + t4 + 4] * 0.125f);
        }
    }

    float of[8][4];
#pragma unroll
    for (int ni = 0; ni < 8; ni++)
#pragma unroll
        for (int j = 0; j < 4; j++) of[ni][j] = 0.f;
    float mrun_a = -1e30f, mrun_b = -1e30f, lrun_a = 0.f, lrun_b = 0.f;

    const float* wbase = wm + ((size_t)b << 20);

    for (int kt = 0; kt < 16; kt++) {
        int k0 = kt << 6;
        __syncthreads();

#pragma unroll
        for (int it = 0; it < 4; it++) {
            int e = (it << 8) + tid;
            int row = e >> 4, c4 = (e & 15) << 2;
            size_t gaddr = (size_t)(b * 1024 + k0 + row) * 1536 + h * 64 + c4;
            float4 kvv = *(const float4*)(kv + gaddr);
            Ks[row][c4 + 0] = f2tf32(kvv.x);
            Ks[row][c4 + 1] = f2tf32(kvv.y);
            Ks[row][c4 + 2] = f2tf32(kvv.z);
            Ks[row][c4 + 3] = f2tf32(kvv.w);
            float4 vv = *(const float4*)(kv + gaddr + 768);
            VTs[c4 + 0][row] = f2tf32(vv.x);
            VTs[c4 + 1][row] = f2tf32(vv.y);
            VTs[c4 + 2][row] = f2tf32(vv.z);
            VTs[c4 + 3][row] = f2tf32(vv.w);
        }
#pragma unroll
        for (int it = 0; it < 8; it++) {
            int e = (it << 8) + tid;
            int row = e >> 4, c4 = (e & 15) << 2;
            float4 wv = *(const float4*)(wbase + (size_t)(q0 + row) * 1024 + k0 + c4);
            Ws[row][c4 + 0] = wv.x;
            Ws[row][c4 + 1] = wv.y;
            Ws[row][c4 + 2] = wv.z;
            Ws[row][c4 + 3] = wv.w;
        }
        __syncthreads();

        // S = Q @ K^T
        float sacc[8][4];
#pragma unroll
        for (int ni = 0; ni < 8; ni++)
#pragma unroll
            for (int j = 0; j < 4; j++) sacc[ni][j] = 0.f;
#pragma unroll
        for (int kf = 0; kf < 8; kf++) {
            int kc = kf << 3;
#pragma unroll
            for (int ni = 0; ni < 8; ni++) {
                uint32_t B[2];
                B[0] = Ks[(ni << 3) + g][kc + t4];
                B[1] = Ks[(ni << 3) + g][kc + t4 + 4];
                mma_tf32(sacc[ni], qf[kf], B);
            }
        }

        // wmap multiply + online softmax
        float m_a = -1e30f, m_b = -1e30f;
#pragma unroll
        for (int ni = 0; ni < 8; ni++) {
            int c0 = (ni << 3) + (t4 << 1);
            sacc[ni][0] *= Ws[r][c0];
            sacc[ni][1] *= Ws[r][c0 + 1];
            sacc[ni][2] *= Ws[r + 8][c0];
            sacc[ni][3] *= Ws[r + 8][c0 + 1];
            m_a = fmaxf(m_a, fmaxf(sacc[ni][0], sacc[ni][1]));
            m_b = fmaxf(m_b, fmaxf(sacc[ni][2], sacc[ni][3]));
        }
        m_a = fmaxf(m_a, __shfl_xor_sync(0xffffffffu, m_a, 1));
        m_a = fmaxf(m_a, __shfl_xor_sync(0xffffffffu, m_a, 2));
        m_b = fmaxf(m_b, __shfl_xor_sync(0xffffffffu, m_b, 1));
        m_b = fmaxf(m_b, __shfl_xor_sync(0xffffffffu, m_b, 2));

        float newm_a = fmaxf(mrun_a, m_a);
        float newm_b = fmaxf(mrun_b, m_b);
        float alpha_a = __expf(mrun_a - newm_a);
        float alpha_b = __expf(mrun_b - newm_b);
        mrun_a = newm_a;
        mrun_b = newm_b;

        float sum_a = 0.f, sum_b = 0.f;
#pragma unroll
        for (int ni = 0; ni < 8; ni++) {
            int c0 = (ni << 3) + (t4 << 1);
            float p0 = __expf(sacc[ni][0] - newm_a);
            float p1 = __expf(sacc[ni][1] - newm_a);
            float p2 = __expf(sacc[ni][2] - newm_b);
            float p3 = __expf(sacc[ni][3] - newm_b);
            sum_a += p0 + p1;
            sum_b += p2 + p3;
            Ps[r][c0] = f2tf32(p0);
            Ps[r][c0 + 1] = f2tf32(p1);
            Ps[r + 8][c0] = f2tf32(p2);
            Ps[r + 8][c0 + 1] = f2tf32(p3);
        }
        sum_a += __shfl_xor_sync(0xffffffffu, sum_a, 1);
        sum_a += __shfl_xor_sync(0xffffffffu, sum_a, 2);
        sum_b += __shfl_xor_sync(0xffffffffu, sum_b, 1);
        sum_b += __shfl_xor_sync(0xffffffffu, sum_b, 2);
        lrun_a = lrun_a * alpha_a + sum_a;
        lrun_b = lrun_b * alpha_b + sum_b;

#pragma unroll
        for (int ni = 0; ni < 8; ni++) {
            of[ni][0] *= alpha_a;
            of[ni][1] *= alpha_a;
            of[ni][2] *= alpha_b;
            of[ni][3] *= alpha_b;
        }
        __syncthreads();

        // O += P @ V
#pragma unroll
        for (int kf = 0; kf < 8; kf++) {
            int kc = kf << 3;
            uint32_t A[4];
            A[0] = Ps[r][kc + t4];
            A[1] = Ps[r + 8][kc + t4];
            A[2] = Ps[r][kc + t4 + 4];
            A[3] = Ps[r + 8][kc + t4 + 4];
#pragma unroll
            for (int ni = 0; ni < 8; ni++) {
                uint32_t B[2];
                B[0] = VTs[(ni << 3) + g][kc + t4];
                B[1] = VTs[(ni << 3) + g][kc + t4 + 4];
                mma_tf32(of[ni], A, B);
            }
        }
    }

    float ia = 1.0f / lrun_a, ib = 1.0f / lrun_b;
#pragma unroll
    for (int ni = 0; ni < 8; ni++) {
        int col = h * 64 + (ni << 3) + (t4 << 1);
        float2 oa = make_float2(of[ni][0] * ia, of[ni][1] * ia);
        float2 ob = make_float2(of[ni][2] * ib, of[ni][3] * ib);
        *(float2*)(att_out + (size_t)(b * 1024 + q0 + r) * 768 + col) = oa;
        *(float2*)(att_out + (size_t)(b * 1024 + q0 + r + 8) * 768 + col) = ob;
    }
}

// =========================================================================
// epipolar parameter setup (per dir,b)
// =========================================================================
__global__ void setup_params_kernel(const float* __restrict__ intr,
                                    const float* __restrict__ c2w) {
    int t = threadIdx.x;
    if (t >= 8) return;
    int dir = t >> 2, b = t & 3;

    float k3[3][3];
    const float Wf = 32.0f * 16.0f / 9.0f;
    for (int i = 0; i < 3; i++)
        for (int j = 0; j < 3; j++)
            k3[i][j] = intr[b * 16 + i * 4 + j];
    for (int j = 0; j < 3; j++) { k3[0][j] *= Wf; k3[1][j] *= 32.0f; }
    k3[0][2] = 16.0f; k3[1][2] = 16.0f;

    int si = (dir == 0) ? 1 : 0;
    int ti = (dir == 0) ? 0 : 1;
    const float* S = c2w + (si * 4 + b) * 16;
    const float* T = c2w + (ti * 4 + b) * 16;
    float sr[3][3], st[3], tr[3][3], tt[3];
    for (int i = 0; i < 3; i++) {
        for (int j = 0; j < 3; j++) { sr[i][j] = S[i * 4 + j]; tr[i][j] = T[i * 4 + j]; }
        st[i] = S[i * 4 + 3]; tt[i] = T[i * 4 + 3];
    }
    float det = tr[0][0] * (tr[1][1] * tr[2][2] - tr[1][2] * tr[2][1])
              - tr[0][1] * (tr[1][0] * tr[2][2] - tr[1][2] * tr[2][0])
              + tr[0][2] * (tr[1][0] * tr[2][1] - tr[1][1] * tr[2][0]);
    float id = 1.0f / det;
    float ti3[3][3];
    ti3[0][0] = (tr[1][1] * tr[2][2] - tr[1][2] * tr[2][1]) * id;
    ti3[0][1] = (tr[0][2] * tr[2][1] - tr[0][1] * tr[2][2]) * id;
    ti3[0][2] = (tr[0][1] * tr[1][2] - tr[0][2] * tr[1][1]) * id;
    ti3[1][0] = (tr[1][2] * tr[2][0] - tr[1][0] * tr[2][2]) * id;
    ti3[1][1] = (tr[0][0] * tr[2][2] - tr[0][2] * tr[2][0]) * id;
    ti3[1][2] = (tr[0][2] * tr[1][0] - tr[0][0] * tr[1][2]) * id;
    ti3[2][0] = (tr[1][0] * tr[2][1] - tr[1][1] * tr[2][0]) * id;
    ti3[2][1] = (tr[0][1] * tr[2][0] - tr[0][0] * tr[2][1]) * id;
    ti3[2][2] = (tr[0][0] * tr[1][1] - tr[0][1] * tr[1][0]) * id;

    float TR[3][3], Mm[3][3];
    for (int i = 0; i < 3; i++)
        for (int j = 0; j < 3; j++) {
            float s = 0.f;
            for (int kk = 0; kk < 3; kk++) s += ti3[i][kk] * sr[kk][j];
            TR[i][j] = s;
        }
    for (int i = 0; i < 3; i++)
        for (int j = 0; j < 3; j++) {
            float s = 0.f;
            for (int kk = 0; kk < 3; kk++) s += k3[i][kk] * TR[kk][j];
            Mm[i][j] = s;
        }
    float o2[3], tv[3];
    for (int i = 0; i < 3; i++) {
        float s = 0.f;
        for (int kk = 0; kk < 3; kk++) s += ti3[i][kk] * st[kk];
        o2[i] = s - tt[i];
    }
    for (int i = 0; i < 3; i++) {
        float s = 0.f;
        for (int kk = 0; kk < 3; kk++) s += k3[i][kk] * o2[kk];
        tv[i] = s;
    }
    float* P = g_params[t];
    P[0] = Mm[0][0]; P[1] = Mm[0][1]; P[2] = Mm[0][2];
    P[3] = Mm[1][0]; P[4] = Mm[1][1]; P[5] = Mm[1][2];
    P[6] = Mm[2][0]; P[7] = Mm[2][1]; P[8] = Mm[2][2];
    P[9] = tv[0]; P[10] = tv[1]; P[11] = tv[2];
    P[12] = k3[0][0]; P[13] = k3[1][1]; P[14] = k3[0][2]; P[15] = k3[1][2];
}

// =========================================================================
// row params + row-max flag (no ep storage): aux[row][8] =
//   ax, ay, az, ox, oy, bz, inv_vlen, flag(1.0 if whole row -> 1.0)
// =========================================================================
__global__ void rowparams_kernel(float* __restrict__ aux) {
    int i = blockIdx.x, b = blockIdx.y, dir = blockIdx.z;
    const float* P = g_params[dir * 4 + b];
    float M0 = P[0], M1 = P[1], M2 = P[2], M3 = P[3], M4 = P[4], M5 = P[5],
          M6 = P[6], M7 = P[7], M8 = P[8];
    float tv0 = P[9], tv1 = P[10], tv2 = P[11];
    float fx = P[12], fy = P[13], cx = P[14], cy = P[15];

    float ncx = ((float)(i & 31) - cx) / fx;
    float ncy = ((float)(i >> 5) - cy) / fy;
    float pux = M0 * ncx + M1 * ncy + M2 + tv0;
    float puy = M3 * ncx + M4 * ncy + M5 + tv1;
    float puz = M6 * ncx + M7 * ncy + M8 + tv2;
    float invz = 1.0f / (puz + 1e-6f);
    float px = pux * invz, py = puy * invz, pz = puz * invz;
    float ozi = 1.0f / tv2;
    float ox = tv0 * ozi, oy = tv1 * ozi, oz = tv2 * ozi;
    float ax = px - ox, ay = py - oy, az = pz - oz;
    float vlen2 = ax * ax + ay * ay + az * az;
    float bz = 1.0f - oz;

    int tid = threadIdx.x;
    float minA2 = 1e30f;
#pragma unroll
    for (int it = 0; it < 4; it++) {
        int j = tid + it * 256;
        float bx = (float)(j & 31) - ox;
        float by = (float)(j >> 5) - oy;
        float crx = ay * bz - az * by;
        float cry = az * bx - ax * bz;
        float crz = ax * by - ay * bx;
        float a2 = crx * crx + cry * cry + crz * crz;
        minA2 = fminf(minA2, a2);
    }
    __shared__ float red[256];
    red[tid] = minA2;
    __syncthreads();
    for (int s = 128; s > 0; s >>= 1) {
        if (tid < s) red[tid] = fminf(red[tid], red[tid + s]);
        __syncthreads();
    }
    if (tid == 0) {
        // row_max(dw) < 0.5  <=>  min dist > 0.5  <=>  minA2 > 0.25 * vlen2
        float flag = (red[0] > 0.25f * vlen2) ? 1.0f : 0.0f;
        float* dst = aux + ((size_t)((dir * 4 + b) * 1024 + i)) * 8;
        dst[0] = ax; dst[1] = ay; dst[2] = az;
        dst[3] = ox; dst[4] = oy; dst[5] = bz;
        dst[6] = rsqrtf(vlen2);
        dst[7] = flag;
    }
}

// =========================================================================
// fused wmap: recompute dw from row params, write wm + 12-head broadcast
// =========================================================================
__device__ __forceinline__ float eval_dw(const float* __restrict__ p, int j) {
    if (p[7] != 0.0f) return 1.0f;
    float bx = (float)(j & 31) - p[3];
    float by = (float)(j >> 5) - p[4];
    float bz = p[5];
    float ax = p[0], ay = p[1], az = p[2];
    float crx = ay * bz - az * by;
    float cry = az * bx - ax * bz;
    float crz = ax * by - ay * bx;
    float dist = sqrtf(crx * crx + cry * cry + crz * crz) * p[6];
    return 1.0f / (1.0f + expf(50.0f * (dist - 0.5f)));
}

__global__ void wmap_kernel(const float* __restrict__ aux,
                            float* __restrict__ wm,
                            float* __restrict__ out_wm) {
    int b = blockIdx.z;
    int I0 = blockIdx.y << 5, J0 = blockIdx.x << 5;
    int tx = threadIdx.x, ty = threadIdx.y;
    int i = I0 + ty, j = J0 + tx;
    const float* p1 = aux + ((size_t)(b * 1024 + i)) * 8;
    const float* p2 = aux + ((size_t)((4 + b) * 1024 + j)) * 8;
    float w = eval_dw(p1, j) * eval_dw(p2, i);
    size_t off = (size_t)i * 1024 + j;
    wm[((size_t)b << 20) + off] = w;
#pragma unroll
    for (int h = 0; h < 12; h++)
        out_wm[((size_t)(b * 12 + h) << 20) + off] = w;
}

// =========================================================================
// layernorm: warp per row; gam==null -> plain normalize; res optional
// =========================================================================
__global__ void ln_kernel(const float* __restrict__ in, const float* __restrict__ res,
                          const float* __restrict__ gam, const float* __restrict__ bet,
                          float* __restrict__ out) {
    int row = (blockIdx.x << 3) + (threadIdx.x >> 5);
    int lane = threadIdx.x & 31;
    const float* p = in + (size_t)row * 768;
    float v[24];
    float s = 0.f;
#pragma unroll
    for (int it = 0; it < 24; it++) {
        int c = lane + (it << 5);
        v[it] = p[c];
        if (res) v[it] += res[(size_t)row * 768 + c];
        s += v[it];
    }
#pragma unroll
    for (int o = 16; o > 0; o >>= 1) s += __shfl_xor_sync(0xffffffffu, s, o);
    float mu = s * (1.0f / 768.0f);
    float qsum = 0.f;
#pragma unroll
    for (int it = 0; it < 24; it++) {
        float d = v[it] - mu;
        qsum += d * d;
    }
#pragma unroll
    for (int o = 16; o > 0; o >>= 1) qsum += __shfl_xor_sync(0xffffffffu, qsum, o);
    float rstd = rsqrtf(qsum * (1.0f / 768.0f) + 1e-5f);
#pragma unroll
    for (int it = 0; it < 24; it++) {
        int c = lane + (it << 5);
        float val = (v[it] - mu) * rstd;
        if (gam) val = val * gam[c] + bet[c];
        out[(size_t)row * 768 + c] = val;
    }
}

// =========================================================================
// launch
// =========================================================================
extern "C" void kernel_launch(void* const* d_in, const int* in_sizes, int n_in,
                              void* d_out, int out_size) {
    const float* x      = (const float*)d_in[0];
    const float* src    = (const float*)d_in[1];
    const float* intr   = (const float*)d_in[2];
    const float* c2w    = (const float*)d_in[3];
    const float* lnq_g  = (const float*)d_in[4];
    const float* lnq_b  = (const float*)d_in[5];
    const float* Wq     = (const float*)d_in[6];
    const float* bq     = (const float*)d_in[7];
    const float* lnk_g  = (const float*)d_in[8];
    const float* lnk_b  = (const float*)d_in[9];
    const float* Wk     = (const float*)d_in[10];
    const float* bk     = (const float*)d_in[11];
    const float* lnv_g  = (const float*)d_in[12];
    const float* lnv_b  = (const float*)d_in[13];
    const float* Wv     = (const float*)d_in[14];
    const float* bv     = (const float*)d_in[15];
    const float* Wp     = (const float*)d_in[16];
    const float* bp     = (const float*)d_in[17];
    const float* pre_g  = (const float*)d_in[18];
    const float* pre_b  = (const float*)d_in[19];
    const float* W1     = (const float*)d_in[20];
    const float* b1     = (const float*)d_in[21];
    const float* W2     = (const float*)d_in[22];
    const float* b2     = (const float*)d_in[23];
    const float* post_g = (const float*)d_in[24];
    const float* post_b = (const float*)d_in[25];

    float* out_z  = (float*)d_out;
    float* out_wm = out_z + (size_t)4 * 1024 * 768;

    void* sp = nullptr;
    cudaGetSymbolAddress(&sp, g_scratch);
    float* base = (float*)sp;
    float* aux  = base + OFF_AUX;
    float* wmb  = base + OFF_WM;
    float* nx   = base + OFF_NX;
    float* ns   = base + OFF_NS;
    float* qb   = base + OFF_Q;
    float* kvb  = base + OFF_KV;
    float* att  = base + OFF_ATT;
    float* p0   = base + OFF_P0;
    float* z0   = base + OFF_Z0;
    float* hid  = base + OFF_HID;
    float* wqt  = base + OFF_WQT;
    float* wkvt = base + OFF_WKVT;
    float* wpt  = base + OFF_WPT;
    float* w1t  = base + OFF_W1T;
    float* w2t  = base + OFF_W2T;
    float* bq2  = base + OFF_BQ2;
    float* bkv2 = base + OFF_BKV2;

    cudaFuncSetAttribute(attn_mma_kernel,
                         cudaFuncAttributeMaxDynamicSharedMemorySize, 103424);

    dim3 tb(32, 32);
    // scaled transposes (fold LN gain into weights)
    transpose_scale_kernel<<<dim3(24, 24), tb>>>(Wq, lnq_g, wqt, 768, 768);
    transpose_scale_kernel<<<dim3(24, 24), tb>>>(Wk, lnk_g, wkvt, 768, 768);
    transpose_scale_kernel<<<dim3(24, 24), tb>>>(Wv, lnv_g, wkvt + (size_t)768 * 768, 768, 768);
    transpose_scale_kernel<<<dim3(24, 24), tb>>>(Wp, nullptr, wpt, 768, 768);
    transpose_scale_kernel<<<dim3(48, 24), tb>>>(W1, nullptr, w1t, 768, 1536);
    transpose_scale_kernel<<<dim3(24, 48), tb>>>(W2, nullptr, w2t, 1536, 768);

    // folded biases
    fold_bias_kernel<<<3, 256>>>(bq, lnq_b, Wq, bq2, 768, 768);
    fold_bias_kernel<<<3, 256>>>(bk, lnk_b, Wk, bkv2, 768, 768);
    fold_bias_kernel<<<3, 256>>>(bv, lnv_b, Wv, bkv2 + 768, 768, 768);

    // epipolar weighting
    setup_params_kernel<<<1, 8>>>(intr, c2w);
    rowparams_kernel<<<dim3(1024, 4, 2), 256>>>(aux);
    wmap_kernel<<<dim3(32, 32, 4), tb>>>(aux, wmb, out_wm);

    // plain LNs (affine folded into weights)
    ln_kernel<<<512, 256>>>(x, nullptr, nullptr, nullptr, nx);
    ln_kernel<<<512, 256>>>(src, nullptr, nullptr, nullptr, ns);

    // projections
    gemm_mma_kernel<<<dim3(6, 32), 256>>>(nx, wqt, bq2, qb, 4096, 768, 768, 0);
    gemm_mma_kernel<<<dim3(12, 32), 256>>>(ns, wkvt, bkv2, kvb, 4096, 1536, 768, 0);

    // attention
    attn_mma_kernel<<<dim3(8, 48), 256, 103424>>>(qb, kvb, wmb, att);

    // output projection + MLP
    gemm_mma_kernel<<<dim3(6, 32), 256>>>(att, wpt, bp, p0, 4096, 768, 768, 0);
    ln_kernel<<<512, 256>>>(p0, nullptr, pre_g, pre_b, z0);
    gemm_mma_kernel<<<dim3(12, 32), 256>>>(z0, w1t, b1, hid, 4096, 1536, 768, 1);
    gemm_mma_kernel<<<dim3(6, 32), 256>>>(hid, w2t, b2, p0, 4096, 768, 1536, 0);
    ln_kernel<<<512, 256>>>(p0, z0, post_g, post_b, out_z);
}